// round 14
// baseline (speedup 1.0000x reference)
#include <cuda_runtime.h>
#include <cuda_fp16.h>
#include <cstdint>

#define NSEG 4096
#define DIM  128
#define C_EXP2  14.426950408889634f   // (1/T)/ln2 = 10/ln2
#define EXP10   22026.465794806718f   // exp(1/T)
#define LN2     0.6931471805599453f

// ---------------- device scratch (static: no allocations allowed) ----------
__device__ __half g_Eh[16777216];            // exp(S/T) fp16 [4096][4096], 32 MB
__device__ float g_rowL[NSEG];               // per-row log-sum partial
__device__ float g_Pdiag[32];                // per-diag-tile sum of S[i,j]/T

__device__ __forceinline__ uint32_t smem_u32(const void* p) {
    uint32_t a;
    asm("{ .reg .u64 t; cvta.to.shared.u64 t, %1; cvt.u32.u64 %0, t; }" : "=r"(a) : "l"(p));
    return a;
}
#define LDSM_X4(r0, r1, r2, r3, addr) \
    asm volatile("ldmatrix.sync.aligned.m8n8.x4.shared.b16 {%0,%1,%2,%3}, [%4];" \
        : "=r"(r0), "=r"(r1), "=r"(r2), "=r"(r3) : "r"(addr))
#define MOVM_T(d, s) \
    asm("movmatrix.sync.aligned.m8n8.trans.b16 %0, %1;" : "=r"(d) : "r"(s))

// ---------------- kernel 1: fp16 HMMA GEMM (upper-tri) with fused norm -----
// Each CTA normalizes its own two 128-row slices of feats straight into smem
// (bitwise-identical across CTAs: same instruction sequence per row).
#define LDH 136                       // padded row stride in halfs (272 B)
#define SMEM2 (2 * 128 * LDH * 2)     // 69632 B

__global__ void __launch_bounds__(256, 2) k_gemm_exp(const float* __restrict__ feats) {
    // triangular decode: tile p -> (bi, bj), bi <= bj
    int p = blockIdx.x, bi = 0, cnt = 32;
    while (p >= cnt) { p -= cnt; ++bi; --cnt; }
    const int bj = bi + p;
    const bool diag = (bi == bj);

    extern __shared__ char smem[];
    __half* As = reinterpret_cast<__half*>(smem);
    __half* Bs = As + 128 * LDH;
    const int tid = threadIdx.x;
    const int w = tid >> 5, lane = tid & 31;
    const int g = lane >> 2, t = lane & 3;
    const int warp_m = w & 3, warp_n = w >> 2;
    const int rowbase = bi * 128, colbase = bj * 128;

    // ---- fused normalize: warp w handles rows [w*16, w*16+16) of both slices
    #pragma unroll
    for (int sel = 0; sel < 2; ++sel) {
        const float* src = feats + (size_t)(sel ? colbase : rowbase) * DIM;
        __half* dst = sel ? Bs : As;
        const float extra = sel ? 1.0f : C_EXP2;
        #pragma unroll
        for (int rr = 0; rr < 16; rr += 4) {
            float4 v0 = *reinterpret_cast<const float4*>(&src[(w * 16 + rr + 0) * DIM + lane * 4]);
            float4 v1 = *reinterpret_cast<const float4*>(&src[(w * 16 + rr + 1) * DIM + lane * 4]);
            float4 v2 = *reinterpret_cast<const float4*>(&src[(w * 16 + rr + 2) * DIM + lane * 4]);
            float4 v3 = *reinterpret_cast<const float4*>(&src[(w * 16 + rr + 3) * DIM + lane * 4]);
            float s0 = fmaf(v0.x, v0.x, fmaf(v0.y, v0.y, fmaf(v0.z, v0.z, v0.w * v0.w)));
            float s1 = fmaf(v1.x, v1.x, fmaf(v1.y, v1.y, fmaf(v1.z, v1.z, v1.w * v1.w)));
            float s2 = fmaf(v2.x, v2.x, fmaf(v2.y, v2.y, fmaf(v2.z, v2.z, v2.w * v2.w)));
            float s3 = fmaf(v3.x, v3.x, fmaf(v3.y, v3.y, fmaf(v3.z, v3.z, v3.w * v3.w)));
            #pragma unroll
            for (int off = 16; off > 0; off >>= 1) {
                s0 += __shfl_xor_sync(0xffffffffu, s0, off);
                s1 += __shfl_xor_sync(0xffffffffu, s1, off);
                s2 += __shfl_xor_sync(0xffffffffu, s2, off);
                s3 += __shfl_xor_sync(0xffffffffu, s3, off);
            }
            float ss[4] = {s0, s1, s2, s3};
            float4 vv[4] = {v0, v1, v2, v3};
            #pragma unroll
            for (int j = 0; j < 4; ++j) {
                float sum = ss[j];
                float inv = rsqrtf(sum);
                inv = inv * (1.5f - 0.5f * sum * inv * inv);   // NR refine (same as k_norm)
                float sc = inv * extra;
                float4 v = vv[j];
                __half2 h0 = __floats2half2_rn(v.x * sc, v.y * sc);
                __half2 h1 = __floats2half2_rn(v.z * sc, v.w * sc);
                uint32_t u0 = *reinterpret_cast<uint32_t*>(&h0);
                uint32_t u1 = *reinterpret_cast<uint32_t*>(&h1);
                *reinterpret_cast<uint2*>(&dst[(w * 16 + rr + j) * LDH + lane * 4]) = make_uint2(u0, u1);
            }
        }
    }
    __syncthreads();

    const int mm = lane >> 3;
    const uint32_t As_b = smem_u32(As), Bs_b = smem_u32(Bs);
    uint32_t aAddr[2], bAddr[4];
    #pragma unroll
    for (int mt = 0; mt < 2; ++mt)
        aAddr[mt] = As_b + (uint32_t)(((warp_m * 32 + mt * 16 + (mm & 1) * 8 + (lane & 7)) * LDH
                                       + (mm >> 1) * 8) * 2);
    #pragma unroll
    for (int np = 0; np < 4; ++np)
        bAddr[np] = Bs_b + (uint32_t)(((warp_n * 64 + np * 16 + (mm >> 1) * 8 + (lane & 7)) * LDH
                                       + (mm & 1) * 8) * 2);

    float c[2][8][4];
    #pragma unroll
    for (int mt = 0; mt < 2; ++mt)
        #pragma unroll
        for (int nt = 0; nt < 8; ++nt)
            #pragma unroll
            for (int q = 0; q < 4; ++q) c[mt][nt][q] = 0.f;

    #pragma unroll
    for (int ks = 0; ks < 8; ++ks) {
        const uint32_t koff = ks * 32;
        uint32_t a[2][4], b[4][4];
        #pragma unroll
        for (int mt = 0; mt < 2; ++mt)
            LDSM_X4(a[mt][0], a[mt][1], a[mt][2], a[mt][3], aAddr[mt] + koff);
        #pragma unroll
        for (int np = 0; np < 4; ++np)
            LDSM_X4(b[np][0], b[np][1], b[np][2], b[np][3], bAddr[np] + koff);
        #pragma unroll
        for (int mt = 0; mt < 2; ++mt)
            #pragma unroll
            for (int nt = 0; nt < 8; ++nt)
                asm volatile(
                    "mma.sync.aligned.m16n8k16.row.col.f32.f16.f16.f32 "
                    "{%0,%1,%2,%3}, {%4,%5,%6,%7}, {%8,%9}, {%0,%1,%2,%3};"
                    : "+f"(c[mt][nt][0]), "+f"(c[mt][nt][1]),
                      "+f"(c[mt][nt][2]), "+f"(c[mt][nt][3])
                    : "r"(a[mt][0]), "r"(a[mt][1]), "r"(a[mt][2]), "r"(a[mt][3]),
                      "r"(b[nt >> 1][(nt & 1) * 2]), "r"(b[nt >> 1][(nt & 1) * 2 + 1]));
    }

    // epilogue: acc already = S*C_EXP2; f16x2 ex2; forced-diag; stores.
    const uint32_t hE  = (uint32_t)__half_as_ushort(__float2half_rn(EXP10));
    float pacc = 0.f;
    #pragma unroll
    for (int mt = 0; mt < 2; ++mt) {
        const int r0v = warp_m * 32 + mt * 16;
        #pragma unroll
        for (int nt = 0; nt < 8; ++nt) {
            const int c0v = warp_n * 64 + nt * 8;
            uint32_t alo, ahi, elo, ehi;
            asm("cvt.rn.f16x2.f32 %0, %1, %2;" : "=r"(alo) : "f"(c[mt][nt][1]), "f"(c[mt][nt][0]));
            asm("cvt.rn.f16x2.f32 %0, %1, %2;" : "=r"(ahi) : "f"(c[mt][nt][3]), "f"(c[mt][nt][2]));
            asm("ex2.approx.f16x2 %0, %1;" : "=r"(elo) : "r"(alo));
            asm("ex2.approx.f16x2 %0, %1;" : "=r"(ehi) : "r"(ahi));
            const int rl = r0v + g, cl = c0v + 2 * t;
            if (diag) {
                if (rl == cl)         elo = (elo & 0xFFFF0000u) | hE;
                if (rl == cl + 1)     elo = (elo & 0x0000FFFFu) | (hE << 16);
                if (rl + 8 == cl)     ehi = (ehi & 0xFFFF0000u) | hE;
                if (rl + 8 == cl + 1) ehi = (ehi & 0x0000FFFFu) | (hE << 16);
                if ((rl >> 2) == (cl >> 2)) {           // cl even -> cl+1 same 4-block
                    if (rl != cl)     pacc += c[mt][nt][0];
                    if (rl != cl + 1) pacc += c[mt][nt][1];
                }
                if (((rl + 8) >> 2) == (cl >> 2)) {
                    if (rl + 8 != cl)     pacc += c[mt][nt][2];
                    if (rl + 8 != cl + 1) pacc += c[mt][nt][3];
                }
            }
            *reinterpret_cast<uint32_t*>(&g_Eh[(size_t)(rowbase + rl) * NSEG + colbase + cl])     = elo;
            *reinterpret_cast<uint32_t*>(&g_Eh[(size_t)(rowbase + rl + 8) * NSEG + colbase + cl]) = ehi;
            if (!diag) {
                uint32_t tlo, thi;
                MOVM_T(tlo, elo);
                MOVM_T(thi, ehi);
                *reinterpret_cast<uint32_t*>(
                    &g_Eh[(size_t)(colbase + c0v + g) * NSEG + rowbase + r0v + 2 * t])     = tlo;
                *reinterpret_cast<uint32_t*>(
                    &g_Eh[(size_t)(colbase + c0v + g) * NSEG + rowbase + r0v + 8 + 2 * t]) = thi;
            }
        }
    }
    if (diag) {   // block-uniform branch: reduce pacc -> g_Pdiag[bi] (S/T = acc*ln2)
        __shared__ float psred[8];
        #pragma unroll
        for (int off = 16; off > 0; off >>= 1) pacc += __shfl_down_sync(0xffffffffu, pacc, off);
        if (lane == 0) psred[w] = pacc;
        __syncthreads();
        if (tid == 0) {
            float s = 0.f;
            #pragma unroll
            for (int ww = 0; ww < 8; ++ww) s += psred[ww];
            g_Pdiag[bi] = s * LN2;
        }
    }
}

// ---------------- kernel 2: per-row loss (computes own RS; product trick) --
__global__ void k_loss() {
    const int r = blockIdx.x;
    const int t = threadIdx.x;
    const int gr = r >> 2, kk = r & 3;
    const uint4* Er = reinterpret_cast<const uint4*>(&g_Eh[(size_t)r * NSEG]);
    const float EXP10S = __half2float(__float2half_rn(EXP10));  // matches forced diag

    uint4 u0 = Er[t], u1 = Er[t + 256];

    float e[16];
    {
        const uint32_t uu[8] = {u0.x, u0.y, u0.z, u0.w, u1.x, u1.y, u1.z, u1.w};
        #pragma unroll
        for (int i = 0; i < 8; ++i) {
            float2 f = __half22float2(*reinterpret_cast<const __half2*>(&uu[i]));
            e[2 * i] = f.x; e[2 * i + 1] = f.y;
        }
    }
    float s01[4], s23[4], gs[4];
    #pragma unroll
    for (int gi = 0; gi < 4; ++gi) {
        s01[gi] = e[4 * gi] + e[4 * gi + 1];
        s23[gi] = e[4 * gi + 2] + e[4 * gi + 3];
        gs[gi]  = s01[gi] + s23[gi];
    }
    // block reduce -> full row sum rs
    __shared__ float sred[8];
    __shared__ float s_rs;
    float tsum = (gs[0] + gs[1]) + (gs[2] + gs[3]);
    #pragma unroll
    for (int off = 16; off > 0; off >>= 1) tsum += __shfl_xor_sync(0xffffffffu, tsum, off);
    if ((t & 31) == 0) sred[t >> 5] = tsum;
    __syncthreads();
    if (t == 0) {
        float a = 0.f;
        #pragma unroll
        for (int ww = 0; ww < 8; ++ww) a += sred[ww];
        s_rs = a;
    }
    __syncthreads();
    const float rsm = s_rs - EXP10S;

    const int gcols[4] = {2 * t, 2 * t + 1, 512 + 2 * t, 513 + 2 * t};
    float acc = 0.f;
    #pragma unroll
    for (int gi = 0; gi < 4; ++gi) {
        const float* eg = &e[4 * gi];
        const float base = rsm - gs[gi];
        if (gcols[gi] != gr) {
            float pr = (base + s01[gi]) * (base + s23[gi]);
            pr *= (base + (eg[0] + eg[2]));
            pr *= (base + (eg[0] + eg[3]));
            pr *= (base + (eg[1] + eg[2]));
            pr *= (base + (eg[1] + eg[3]));
            acc += __logf(pr);
        } else {
            const float b2 = base + eg[kk];
            float pr = 1.f;
            #pragma unroll
            for (int m = 0; m < 4; ++m)
                if (m != kk) pr *= (b2 + eg[m]);
            acc += __logf(pr);
        }
    }

    #pragma unroll
    for (int off = 16; off > 0; off >>= 1) acc += __shfl_down_sync(0xffffffffu, acc, off);
    __shared__ float wa[8];
    if ((t & 31) == 0) wa[t >> 5] = acc;
    __syncthreads();
    if (t == 0) {
        float a = 0.f;
        #pragma unroll
        for (int ww = 0; ww < 8; ++ww) a += wa[ww];
        g_rowL[r] = a;
    }
}

// ---------------- kernel 3: parallel deterministic combine -----------------
__global__ void k_finalize(float* __restrict__ out) {
    const int t = threadIdx.x;
    const float4* p = reinterpret_cast<const float4*>(g_rowL);

    float4 v0 = p[t], v1 = p[t + 256], v2 = p[t + 512], v3 = p[t + 768];
    double a = (double)((v0.x + v0.y) + (v0.z + v0.w))
             + (double)((v1.x + v1.y) + (v1.z + v1.w))
             + (double)((v2.x + v2.y) + (v2.z + v2.w))
             + (double)((v3.x + v3.y) + (v3.z + v3.w));

    #pragma unroll
    for (int off = 16; off > 0; off >>= 1) a += __shfl_down_sync(0xffffffffu, a, off);
    __shared__ double sa[8];
    if ((t & 31) == 0) sa[t >> 5] = a;
    __syncthreads();

    if (t < 32) {
        double s = (t < 8) ? sa[t] : 0.0;
        #pragma unroll
        for (int off = 4; off > 0; off >>= 1) s += __shfl_down_sync(0xffffffffu, s, off);
        double pd = (double)g_Pdiag[t];
        #pragma unroll
        for (int off = 16; off > 0; off >>= 1) pd += __shfl_down_sync(0xffffffffu, pd, off);
        if (t == 0) out[0] = (float)(s * (2.0 / 4094.0) - pd);
    }
}

// ---------------- launch ---------------------------------------------------
extern "C" void kernel_launch(void* const* d_in, const int* in_sizes, int n_in,
                              void* d_out, int out_size) {
    const float* feats = (const float*)d_in[0];
    float* out = (float*)d_out;

    cudaFuncSetAttribute(k_gemm_exp, cudaFuncAttributeMaxDynamicSharedMemorySize, SMEM2);

    k_gemm_exp<<<528, 256, SMEM2>>>(feats);
    k_loss<<<NSEG, 256>>>();
    k_finalize<<<1, 256>>>(out);
}

// round 15
// speedup vs baseline: 1.0653x; 1.0653x over previous
#include <cuda_runtime.h>
#include <cuda_fp16.h>
#include <cstdint>

#define NSEG 4096
#define DIM  128
#define C_EXP2  14.426950408889634f   // (1/T)/ln2 = 10/ln2
#define EXP10   22026.465794806718f   // exp(1/T)
#define LN2     0.6931471805599453f

// ---------------- device scratch (static: no allocations allowed) ----------
__device__ __half g_Eh[16777216];            // exp(S/T) fp16 [4096][4096], 32 MB
__device__ float g_rowL[NSEG];               // per-row log-sum partial
__device__ float g_Pdiag[32];                // per-diag-tile sum of S[i,j]/T

__device__ __forceinline__ uint32_t smem_u32(const void* p) {
    uint32_t a;
    asm("{ .reg .u64 t; cvta.to.shared.u64 t, %1; cvt.u32.u64 %0, t; }" : "=r"(a) : "l"(p));
    return a;
}
#define LDSM_X4(r0, r1, r2, r3, addr) \
    asm volatile("ldmatrix.sync.aligned.m8n8.x4.shared.b16 {%0,%1,%2,%3}, [%4];" \
        : "=r"(r0), "=r"(r1), "=r"(r2), "=r"(r3) : "r"(addr))
#define MOVM_T(d, s) \
    asm("movmatrix.sync.aligned.m8n8.trans.b16 %0, %1;" : "=r"(d) : "r"(s))

// ---------------- kernel 1: fp16 HMMA GEMM (upper-tri) with fused norm -----
#define LDH 136                       // padded row stride in halfs (272 B)
#define SMEM2 (2 * 128 * LDH * 2)     // 69632 B

__global__ void __launch_bounds__(256, 2) k_gemm_exp(const float* __restrict__ feats) {
    // triangular decode: tile p -> (bi, bj), bi <= bj
    int p = blockIdx.x, bi = 0, cnt = 32;
    while (p >= cnt) { p -= cnt; ++bi; --cnt; }
    const int bj = bi + p;
    const bool diag = (bi == bj);

    extern __shared__ char smem[];
    __half* As = reinterpret_cast<__half*>(smem);
    __half* Bs = As + 128 * LDH;
    const int tid = threadIdx.x;
    const int w = tid >> 5, lane = tid & 31;
    const int g = lane >> 2, t = lane & 3;
    const int warp_m = w & 3, warp_n = w >> 2;
    const int rowbase = bi * 128, colbase = bj * 128;

    // ---- fused normalize: warp w handles rows [w*16, w*16+16) of both slices
    #pragma unroll
    for (int sel = 0; sel < 2; ++sel) {
        const float* src = feats + (size_t)(sel ? colbase : rowbase) * DIM;
        __half* dst = sel ? Bs : As;
        const float extra = sel ? 1.0f : C_EXP2;
        #pragma unroll
        for (int rr = 0; rr < 16; rr += 4) {
            float4 v0 = *reinterpret_cast<const float4*>(&src[(w * 16 + rr + 0) * DIM + lane * 4]);
            float4 v1 = *reinterpret_cast<const float4*>(&src[(w * 16 + rr + 1) * DIM + lane * 4]);
            float4 v2 = *reinterpret_cast<const float4*>(&src[(w * 16 + rr + 2) * DIM + lane * 4]);
            float4 v3 = *reinterpret_cast<const float4*>(&src[(w * 16 + rr + 3) * DIM + lane * 4]);
            float s0 = fmaf(v0.x, v0.x, fmaf(v0.y, v0.y, fmaf(v0.z, v0.z, v0.w * v0.w)));
            float s1 = fmaf(v1.x, v1.x, fmaf(v1.y, v1.y, fmaf(v1.z, v1.z, v1.w * v1.w)));
            float s2 = fmaf(v2.x, v2.x, fmaf(v2.y, v2.y, fmaf(v2.z, v2.z, v2.w * v2.w)));
            float s3 = fmaf(v3.x, v3.x, fmaf(v3.y, v3.y, fmaf(v3.z, v3.z, v3.w * v3.w)));
            #pragma unroll
            for (int off = 16; off > 0; off >>= 1) {
                s0 += __shfl_xor_sync(0xffffffffu, s0, off);
                s1 += __shfl_xor_sync(0xffffffffu, s1, off);
                s2 += __shfl_xor_sync(0xffffffffu, s2, off);
                s3 += __shfl_xor_sync(0xffffffffu, s3, off);
            }
            float ss[4] = {s0, s1, s2, s3};
            float4 vv[4] = {v0, v1, v2, v3};
            #pragma unroll
            for (int j = 0; j < 4; ++j) {
                float sum = ss[j];
                float inv = rsqrtf(sum);
                inv = inv * (1.5f - 0.5f * sum * inv * inv);   // NR refine
                float sc = inv * extra;
                float4 v = vv[j];
                __half2 h0 = __floats2half2_rn(v.x * sc, v.y * sc);
                __half2 h1 = __floats2half2_rn(v.z * sc, v.w * sc);
                uint32_t u0 = *reinterpret_cast<uint32_t*>(&h0);
                uint32_t u1 = *reinterpret_cast<uint32_t*>(&h1);
                *reinterpret_cast<uint2*>(&dst[(w * 16 + rr + j) * LDH + lane * 4]) = make_uint2(u0, u1);
            }
        }
    }
    __syncthreads();

    const int mm = lane >> 3;
    const uint32_t As_b = smem_u32(As), Bs_b = smem_u32(Bs);
    uint32_t aAddr[2], bAddr[4];
    #pragma unroll
    for (int mt = 0; mt < 2; ++mt)
        aAddr[mt] = As_b + (uint32_t)(((warp_m * 32 + mt * 16 + (mm & 1) * 8 + (lane & 7)) * LDH
                                       + (mm >> 1) * 8) * 2);
    #pragma unroll
    for (int np = 0; np < 4; ++np)
        bAddr[np] = Bs_b + (uint32_t)(((warp_n * 64 + np * 16 + (mm >> 1) * 8 + (lane & 7)) * LDH
                                       + (mm & 1) * 8) * 2);

    float c[2][8][4];
    #pragma unroll
    for (int mt = 0; mt < 2; ++mt)
        #pragma unroll
        for (int nt = 0; nt < 8; ++nt)
            #pragma unroll
            for (int q = 0; q < 4; ++q) c[mt][nt][q] = 0.f;

    #pragma unroll
    for (int ks = 0; ks < 8; ++ks) {
        const uint32_t koff = ks * 32;
        uint32_t a[2][4], b[4][4];
        #pragma unroll
        for (int mt = 0; mt < 2; ++mt)
            LDSM_X4(a[mt][0], a[mt][1], a[mt][2], a[mt][3], aAddr[mt] + koff);
        #pragma unroll
        for (int np = 0; np < 4; ++np)
            LDSM_X4(b[np][0], b[np][1], b[np][2], b[np][3], bAddr[np] + koff);
        #pragma unroll
        for (int mt = 0; mt < 2; ++mt)
            #pragma unroll
            for (int nt = 0; nt < 8; ++nt)
                asm volatile(
                    "mma.sync.aligned.m16n8k16.row.col.f32.f16.f16.f32 "
                    "{%0,%1,%2,%3}, {%4,%5,%6,%7}, {%8,%9}, {%0,%1,%2,%3};"
                    : "+f"(c[mt][nt][0]), "+f"(c[mt][nt][1]),
                      "+f"(c[mt][nt][2]), "+f"(c[mt][nt][3])
                    : "r"(a[mt][0]), "r"(a[mt][1]), "r"(a[mt][2]), "r"(a[mt][3]),
                      "r"(b[nt >> 1][(nt & 1) * 2]), "r"(b[nt >> 1][(nt & 1) * 2 + 1]));
    }

    __syncthreads();   // all LDSM reads done; As/Bs become staging areas

    // epilogue: exp in registers (identical bits), stage to smem, flush coalesced
    __half* stD = As;   // direct layout   [128][LDH]
    __half* stT = Bs;   // transposed tile [128][LDH]
    const uint32_t hE  = (uint32_t)__half_as_ushort(__float2half_rn(EXP10));
    float pacc = 0.f;
    #pragma unroll
    for (int mt = 0; mt < 2; ++mt) {
        const int r0v = warp_m * 32 + mt * 16;
        #pragma unroll
        for (int nt = 0; nt < 8; ++nt) {
            const int c0v = warp_n * 64 + nt * 8;
            uint32_t alo, ahi, elo, ehi;
            asm("cvt.rn.f16x2.f32 %0, %1, %2;" : "=r"(alo) : "f"(c[mt][nt][1]), "f"(c[mt][nt][0]));
            asm("cvt.rn.f16x2.f32 %0, %1, %2;" : "=r"(ahi) : "f"(c[mt][nt][3]), "f"(c[mt][nt][2]));
            asm("ex2.approx.f16x2 %0, %1;" : "=r"(elo) : "r"(alo));
            asm("ex2.approx.f16x2 %0, %1;" : "=r"(ehi) : "r"(ahi));
            const int rl = r0v + g, cl = c0v + 2 * t;
            if (diag) {
                if (rl == cl)         elo = (elo & 0xFFFF0000u) | hE;
                if (rl == cl + 1)     elo = (elo & 0x0000FFFFu) | (hE << 16);
                if (rl + 8 == cl)     ehi = (ehi & 0xFFFF0000u) | hE;
                if (rl + 8 == cl + 1) ehi = (ehi & 0x0000FFFFu) | (hE << 16);
                if ((rl >> 2) == (cl >> 2)) {
                    if (rl != cl)     pacc += c[mt][nt][0];
                    if (rl != cl + 1) pacc += c[mt][nt][1];
                }
                if (((rl + 8) >> 2) == (cl >> 2)) {
                    if (rl + 8 != cl)     pacc += c[mt][nt][2];
                    if (rl + 8 != cl + 1) pacc += c[mt][nt][3];
                }
            }
            // stage direct (conflict-free: word offset 4g+t spans all banks)
            *reinterpret_cast<uint32_t*>(&stD[rl * LDH + cl])       = elo;
            *reinterpret_cast<uint32_t*>(&stD[(rl + 8) * LDH + cl]) = ehi;
            if (!diag) {
                uint32_t tlo, thi;
                MOVM_T(tlo, elo);
                MOVM_T(thi, ehi);
                *reinterpret_cast<uint32_t*>(&stT[(c0v + g) * LDH + r0v + 2 * t])     = tlo;
                *reinterpret_cast<uint32_t*>(&stT[(c0v + g) * LDH + r0v + 8 + 2 * t]) = thi;
            }
        }
    }
    __syncthreads();

    // coalesced flush: warp writes 2 complete 256B rows per iteration
    {
        const int frow = tid >> 4;
        const int fcol = (tid & 15) * 8;   // half index, 16B per lane
        #pragma unroll
        for (int it = 0; it < 8; ++it) {
            const int row = it * 16 + frow;
            uint4 v = *reinterpret_cast<const uint4*>(&stD[row * LDH + fcol]);
            *reinterpret_cast<uint4*>(&g_Eh[(size_t)(rowbase + row) * NSEG + colbase + fcol]) = v;
        }
        if (!diag) {
            #pragma unroll
            for (int it = 0; it < 8; ++it) {
                const int row = it * 16 + frow;
                uint4 v = *reinterpret_cast<const uint4*>(&stT[row * LDH + fcol]);
                *reinterpret_cast<uint4*>(&g_Eh[(size_t)(colbase + row) * NSEG + rowbase + fcol]) = v;
            }
        }
    }

    if (diag) {   // block-uniform branch: reduce pacc -> g_Pdiag[bi] (S/T = acc*ln2)
        __shared__ float psred[8];
        #pragma unroll
        for (int off = 16; off > 0; off >>= 1) pacc += __shfl_down_sync(0xffffffffu, pacc, off);
        if (lane == 0) psred[w] = pacc;
        __syncthreads();
        if (tid == 0) {
            float s = 0.f;
            #pragma unroll
            for (int ww = 0; ww < 8; ++ww) s += psred[ww];
            g_Pdiag[bi] = s * LN2;
        }
    }
}

// ---------------- kernel 2: per-row loss (computes own RS; product trick) --
__global__ void k_loss() {
    const int r = blockIdx.x;
    const int t = threadIdx.x;
    const int gr = r >> 2, kk = r & 3;
    const uint4* Er = reinterpret_cast<const uint4*>(&g_Eh[(size_t)r * NSEG]);
    const float EXP10S = __half2float(__float2half_rn(EXP10));  // matches forced diag

    uint4 u0 = Er[t], u1 = Er[t + 256];

    float e[16];
    {
        const uint32_t uu[8] = {u0.x, u0.y, u0.z, u0.w, u1.x, u1.y, u1.z, u1.w};
        #pragma unroll
        for (int i = 0; i < 8; ++i) {
            float2 f = __half22float2(*reinterpret_cast<const __half2*>(&uu[i]));
            e[2 * i] = f.x; e[2 * i + 1] = f.y;
        }
    }
    float s01[4], s23[4], gs[4];
    #pragma unroll
    for (int gi = 0; gi < 4; ++gi) {
        s01[gi] = e[4 * gi] + e[4 * gi + 1];
        s23[gi] = e[4 * gi + 2] + e[4 * gi + 3];
        gs[gi]  = s01[gi] + s23[gi];
    }
    // block reduce -> full row sum rs
    __shared__ float sred[8];
    __shared__ float s_rs;
    float tsum = (gs[0] + gs[1]) + (gs[2] + gs[3]);
    #pragma unroll
    for (int off = 16; off > 0; off >>= 1) tsum += __shfl_xor_sync(0xffffffffu, tsum, off);
    if ((t & 31) == 0) sred[t >> 5] = tsum;
    __syncthreads();
    if (t == 0) {
        float a = 0.f;
        #pragma unroll
        for (int ww = 0; ww < 8; ++ww) a += sred[ww];
        s_rs = a;
    }
    __syncthreads();
    const float rsm = s_rs - EXP10S;

    const int gcols[4] = {2 * t, 2 * t + 1, 512 + 2 * t, 513 + 2 * t};
    float acc = 0.f;
    #pragma unroll
    for (int gi = 0; gi < 4; ++gi) {
        const float* eg = &e[4 * gi];
        const float base = rsm - gs[gi];
        if (gcols[gi] != gr) {
            float pr = (base + s01[gi]) * (base + s23[gi]);
            pr *= (base + (eg[0] + eg[2]));
            pr *= (base + (eg[0] + eg[3]));
            pr *= (base + (eg[1] + eg[2]));
            pr *= (base + (eg[1] + eg[3]));
            acc += __logf(pr);
        } else {
            const float b2 = base + eg[kk];
            float pr = 1.f;
            #pragma unroll
            for (int m = 0; m < 4; ++m)
                if (m != kk) pr *= (b2 + eg[m]);
            acc += __logf(pr);
        }
    }

    #pragma unroll
    for (int off = 16; off > 0; off >>= 1) acc += __shfl_down_sync(0xffffffffu, acc, off);
    __shared__ float wa[8];
    if ((t & 31) == 0) wa[t >> 5] = acc;
    __syncthreads();
    if (t == 0) {
        float a = 0.f;
        #pragma unroll
        for (int ww = 0; ww < 8; ++ww) a += wa[ww];
        g_rowL[r] = a;
    }
}

// ---------------- kernel 3: parallel deterministic combine -----------------
__global__ void k_finalize(float* __restrict__ out) {
    const int t = threadIdx.x;
    const float4* p = reinterpret_cast<const float4*>(g_rowL);

    float4 v0 = p[t], v1 = p[t + 256], v2 = p[t + 512], v3 = p[t + 768];
    double a = (double)((v0.x + v0.y) + (v0.z + v0.w))
             + (double)((v1.x + v1.y) + (v1.z + v1.w))
             + (double)((v2.x + v2.y) + (v2.z + v2.w))
             + (double)((v3.x + v3.y) + (v3.z + v3.w));

    #pragma unroll
    for (int off = 16; off > 0; off >>= 1) a += __shfl_down_sync(0xffffffffu, a, off);
    __shared__ double sa[8];
    if ((t & 31) == 0) sa[t >> 5] = a;
    __syncthreads();

    if (t < 32) {
        double s = (t < 8) ? sa[t] : 0.0;
        #pragma unroll
        for (int off = 4; off > 0; off >>= 1) s += __shfl_down_sync(0xffffffffu, s, off);
        double pd = (double)g_Pdiag[t];
        #pragma unroll
        for (int off = 16; off > 0; off >>= 1) pd += __shfl_down_sync(0xffffffffu, pd, off);
        if (t == 0) out[0] = (float)(s * (2.0 / 4094.0) - pd);
    }
}

// ---------------- launch ---------------------------------------------------
extern "C" void kernel_launch(void* const* d_in, const int* in_sizes, int n_in,
                              void* d_out, int out_size) {
    const float* feats = (const float*)d_in[0];
    float* out = (float*)d_out;

    cudaFuncSetAttribute(k_gemm_exp, cudaFuncAttributeMaxDynamicSharedMemorySize, SMEM2);

    k_gemm_exp<<<528, 256, SMEM2>>>(feats);
    k_loss<<<NSEG, 256>>>();
    k_finalize<<<1, 256>>>(out);
}

// round 16
// speedup vs baseline: 1.0678x; 1.0023x over previous
#include <cuda_runtime.h>
#include <cuda_fp16.h>
#include <cstdint>

#define NSEG 4096
#define DIM  128
#define C_EXP2  14.426950408889634f   // (1/T)/ln2 = 10/ln2
#define EXP10   22026.465794806718f   // exp(1/T)
#define LN2     0.6931471805599453f

// ---------------- device scratch (static: no allocations allowed) ----------
__device__ __half g_Eh[16777216];            // exp(S/T) fp16 [4096][4096], 32 MB
__device__ float g_rowL[NSEG];               // per-row log-sum partial
__device__ float g_Pdiag[32];                // per-diag-tile sum of S[i,j]/T

__device__ __forceinline__ uint32_t smem_u32(const void* p) {
    uint32_t a;
    asm("{ .reg .u64 t; cvta.to.shared.u64 t, %1; cvt.u32.u64 %0, t; }" : "=r"(a) : "l"(p));
    return a;
}
#define LDSM_X4(r0, r1, r2, r3, addr) \
    asm volatile("ldmatrix.sync.aligned.m8n8.x4.shared.b16 {%0,%1,%2,%3}, [%4];" \
        : "=r"(r0), "=r"(r1), "=r"(r2), "=r"(r3) : "r"(addr))
#define MOVM_T(d, s) \
    asm("movmatrix.sync.aligned.m8n8.trans.b16 %0, %1;" : "=r"(d) : "r"(s))

// ---------------- kernel 1: fp16 HMMA GEMM (upper-tri) with fused norm -----
#define LDH 136                       // padded row stride in halfs (272 B)
#define SMEM2 (2 * 128 * LDH * 2)     // 69632 B

__global__ void __launch_bounds__(256, 2) k_gemm_exp(const float* __restrict__ feats) {
    // triangular decode: tile p -> (bi, bj), bi <= bj
    int p = blockIdx.x, bi = 0, cnt = 32;
    while (p >= cnt) { p -= cnt; ++bi; --cnt; }
    const int bj = bi + p;
    const bool diag = (bi == bj);

    extern __shared__ char smem[];
    __half* As = reinterpret_cast<__half*>(smem);
    __half* Bs = As + 128 * LDH;
    const int tid = threadIdx.x;
    const int w = tid >> 5, lane = tid & 31;
    const int g = lane >> 2, t = lane & 3;
    const int warp_m = w & 3, warp_n = w >> 2;
    const int rowbase = bi * 128, colbase = bj * 128;

    // ---- fused normalize: warp w handles rows [w*16, w*16+16) of both slices,
    //      A/B chains interleaved (8-way ILP); diag reuses A registers for B.
    {
        const float* srcA = feats + (size_t)rowbase * DIM;
        const float* srcB = feats + (size_t)colbase * DIM;
        #pragma unroll
        for (int rr = 0; rr < 16; rr += 4) {
            const int r0 = w * 16 + rr;
            float4 va[4], vb[4];
            #pragma unroll
            for (int j = 0; j < 4; ++j)
                va[j] = *reinterpret_cast<const float4*>(&srcA[(r0 + j) * DIM + lane * 4]);
            if (!diag) {
                #pragma unroll
                for (int j = 0; j < 4; ++j)
                    vb[j] = *reinterpret_cast<const float4*>(&srcB[(r0 + j) * DIM + lane * 4]);
            }
            float sa[4], sb[4];
            #pragma unroll
            for (int j = 0; j < 4; ++j)
                sa[j] = fmaf(va[j].x, va[j].x, fmaf(va[j].y, va[j].y,
                        fmaf(va[j].z, va[j].z, va[j].w * va[j].w)));
            if (!diag) {
                #pragma unroll
                for (int j = 0; j < 4; ++j)
                    sb[j] = fmaf(vb[j].x, vb[j].x, fmaf(vb[j].y, vb[j].y,
                            fmaf(vb[j].z, vb[j].z, vb[j].w * vb[j].w)));
                #pragma unroll
                for (int off = 16; off > 0; off >>= 1) {
                    #pragma unroll
                    for (int j = 0; j < 4; ++j) {
                        sa[j] += __shfl_xor_sync(0xffffffffu, sa[j], off);
                        sb[j] += __shfl_xor_sync(0xffffffffu, sb[j], off);
                    }
                }
            } else {
                #pragma unroll
                for (int off = 16; off > 0; off >>= 1) {
                    #pragma unroll
                    for (int j = 0; j < 4; ++j)
                        sa[j] += __shfl_xor_sync(0xffffffffu, sa[j], off);
                }
            }
            #pragma unroll
            for (int j = 0; j < 4; ++j) {
                float suma = sa[j];
                float inva = rsqrtf(suma);
                inva = inva * (1.5f - 0.5f * suma * inva * inva);   // NR refine
                float invb;
                float4 v_b;
                if (diag) { invb = inva; v_b = va[j]; }
                else {
                    float sumb = sb[j];
                    invb = rsqrtf(sumb);
                    invb = invb * (1.5f - 0.5f * sumb * invb * invb);
                    v_b = vb[j];
                }
                float scA = inva * C_EXP2;
                __half2 ha0 = __floats2half2_rn(va[j].x * scA, va[j].y * scA);
                __half2 ha1 = __floats2half2_rn(va[j].z * scA, va[j].w * scA);
                __half2 hb0 = __floats2half2_rn(v_b.x * invb, v_b.y * invb);
                __half2 hb1 = __floats2half2_rn(v_b.z * invb, v_b.w * invb);
                uint32_t uA0 = *reinterpret_cast<uint32_t*>(&ha0);
                uint32_t uA1 = *reinterpret_cast<uint32_t*>(&ha1);
                uint32_t uB0 = *reinterpret_cast<uint32_t*>(&hb0);
                uint32_t uB1 = *reinterpret_cast<uint32_t*>(&hb1);
                *reinterpret_cast<uint2*>(&As[(r0 + j) * LDH + lane * 4]) = make_uint2(uA0, uA1);
                *reinterpret_cast<uint2*>(&Bs[(r0 + j) * LDH + lane * 4]) = make_uint2(uB0, uB1);
            }
        }
    }
    __syncthreads();

    const int mm = lane >> 3;
    const uint32_t As_b = smem_u32(As), Bs_b = smem_u32(Bs);
    uint32_t aAddr[2], bAddr[4];
    #pragma unroll
    for (int mt = 0; mt < 2; ++mt)
        aAddr[mt] = As_b + (uint32_t)(((warp_m * 32 + mt * 16 + (mm & 1) * 8 + (lane & 7)) * LDH
                                       + (mm >> 1) * 8) * 2);
    #pragma unroll
    for (int np = 0; np < 4; ++np)
        bAddr[np] = Bs_b + (uint32_t)(((warp_n * 64 + np * 16 + (mm >> 1) * 8 + (lane & 7)) * LDH
                                       + (mm & 1) * 8) * 2);

    float c[2][8][4];
    #pragma unroll
    for (int mt = 0; mt < 2; ++mt)
        #pragma unroll
        for (int nt = 0; nt < 8; ++nt)
            #pragma unroll
            for (int q = 0; q < 4; ++q) c[mt][nt][q] = 0.f;

    #pragma unroll
    for (int ks = 0; ks < 8; ++ks) {
        const uint32_t koff = ks * 32;
        uint32_t a[2][4], b[4][4];
        #pragma unroll
        for (int mt = 0; mt < 2; ++mt)
            LDSM_X4(a[mt][0], a[mt][1], a[mt][2], a[mt][3], aAddr[mt] + koff);
        #pragma unroll
        for (int np = 0; np < 4; ++np)
            LDSM_X4(b[np][0], b[np][1], b[np][2], b[np][3], bAddr[np] + koff);
        #pragma unroll
        for (int mt = 0; mt < 2; ++mt)
            #pragma unroll
            for (int nt = 0; nt < 8; ++nt)
                asm volatile(
                    "mma.sync.aligned.m16n8k16.row.col.f32.f16.f16.f32 "
                    "{%0,%1,%2,%3}, {%4,%5,%6,%7}, {%8,%9}, {%0,%1,%2,%3};"
                    : "+f"(c[mt][nt][0]), "+f"(c[mt][nt][1]),
                      "+f"(c[mt][nt][2]), "+f"(c[mt][nt][3])
                    : "r"(a[mt][0]), "r"(a[mt][1]), "r"(a[mt][2]), "r"(a[mt][3]),
                      "r"(b[nt >> 1][(nt & 1) * 2]), "r"(b[nt >> 1][(nt & 1) * 2 + 1]));
    }

    __syncthreads();   // all LDSM reads done; As/Bs become staging areas

    // epilogue: exp in registers (identical bits), stage to smem, flush coalesced
    __half* stD = As;   // direct layout   [128][LDH]
    __half* stT = Bs;   // transposed tile [128][LDH]
    const uint32_t hE  = (uint32_t)__half_as_ushort(__float2half_rn(EXP10));
    float pacc = 0.f;
    #pragma unroll
    for (int mt = 0; mt < 2; ++mt) {
        const int r0v = warp_m * 32 + mt * 16;
        #pragma unroll
        for (int nt = 0; nt < 8; ++nt) {
            const int c0v = warp_n * 64 + nt * 8;
            uint32_t alo, ahi, elo, ehi;
            asm("cvt.rn.f16x2.f32 %0, %1, %2;" : "=r"(alo) : "f"(c[mt][nt][1]), "f"(c[mt][nt][0]));
            asm("cvt.rn.f16x2.f32 %0, %1, %2;" : "=r"(ahi) : "f"(c[mt][nt][3]), "f"(c[mt][nt][2]));
            asm("ex2.approx.f16x2 %0, %1;" : "=r"(elo) : "r"(alo));
            asm("ex2.approx.f16x2 %0, %1;" : "=r"(ehi) : "r"(ahi));
            const int rl = r0v + g, cl = c0v + 2 * t;
            if (diag) {
                if (rl == cl)         elo = (elo & 0xFFFF0000u) | hE;
                if (rl == cl + 1)     elo = (elo & 0x0000FFFFu) | (hE << 16);
                if (rl + 8 == cl)     ehi = (ehi & 0xFFFF0000u) | hE;
                if (rl + 8 == cl + 1) ehi = (ehi & 0x0000FFFFu) | (hE << 16);
                if ((rl >> 2) == (cl >> 2)) {
                    if (rl != cl)     pacc += c[mt][nt][0];
                    if (rl != cl + 1) pacc += c[mt][nt][1];
                }
                if (((rl + 8) >> 2) == (cl >> 2)) {
                    if (rl + 8 != cl)     pacc += c[mt][nt][2];
                    if (rl + 8 != cl + 1) pacc += c[mt][nt][3];
                }
            }
            // stage direct (conflict-free: word offset 4g+t spans all banks)
            *reinterpret_cast<uint32_t*>(&stD[rl * LDH + cl])       = elo;
            *reinterpret_cast<uint32_t*>(&stD[(rl + 8) * LDH + cl]) = ehi;
            if (!diag) {
                uint32_t tlo, thi;
                MOVM_T(tlo, elo);
                MOVM_T(thi, ehi);
                *reinterpret_cast<uint32_t*>(&stT[(c0v + g) * LDH + r0v + 2 * t])     = tlo;
                *reinterpret_cast<uint32_t*>(&stT[(c0v + g) * LDH + r0v + 8 + 2 * t]) = thi;
            }
        }
    }
    __syncthreads();

    // coalesced flush: warp writes 2 complete 256B rows per iteration
    {
        const int frow = tid >> 4;
        const int fcol = (tid & 15) * 8;   // half index, 16B per lane
        #pragma unroll
        for (int it = 0; it < 8; ++it) {
            const int row = it * 16 + frow;
            uint4 v = *reinterpret_cast<const uint4*>(&stD[row * LDH + fcol]);
            *reinterpret_cast<uint4*>(&g_Eh[(size_t)(rowbase + row) * NSEG + colbase + fcol]) = v;
        }
        if (!diag) {
            #pragma unroll
            for (int it = 0; it < 8; ++it) {
                const int row = it * 16 + frow;
                uint4 v = *reinterpret_cast<const uint4*>(&stT[row * LDH + fcol]);
                *reinterpret_cast<uint4*>(&g_Eh[(size_t)(colbase + row) * NSEG + rowbase + fcol]) = v;
            }
        }
    }

    if (diag) {   // block-uniform branch: reduce pacc -> g_Pdiag[bi] (S/T = acc*ln2)
        __shared__ float psred[8];
        #pragma unroll
        for (int off = 16; off > 0; off >>= 1) pacc += __shfl_down_sync(0xffffffffu, pacc, off);
        if (lane == 0) psred[w] = pacc;
        __syncthreads();
        if (tid == 0) {
            float s = 0.f;
            #pragma unroll
            for (int ww = 0; ww < 8; ++ww) s += psred[ww];
            g_Pdiag[bi] = s * LN2;
        }
    }
}

// ---------------- kernel 2: per-row loss (computes own RS; product trick) --
__global__ void k_loss() {
    const int r = blockIdx.x;
    const int t = threadIdx.x;
    const int gr = r >> 2, kk = r & 3;
    const uint4* Er = reinterpret_cast<const uint4*>(&g_Eh[(size_t)r * NSEG]);
    const float EXP10S = __half2float(__float2half_rn(EXP10));  // matches forced diag

    uint4 u0 = Er[t], u1 = Er[t + 256];

    float e[16];
    {
        const uint32_t uu[8] = {u0.x, u0.y, u0.z, u0.w, u1.x, u1.y, u1.z, u1.w};
        #pragma unroll
        for (int i = 0; i < 8; ++i) {
            float2 f = __half22float2(*reinterpret_cast<const __half2*>(&uu[i]));
            e[2 * i] = f.x; e[2 * i + 1] = f.y;
        }
    }
    float s01[4], s23[4], gs[4];
    #pragma unroll
    for (int gi = 0; gi < 4; ++gi) {
        s01[gi] = e[4 * gi] + e[4 * gi + 1];
        s23[gi] = e[4 * gi + 2] + e[4 * gi + 3];
        gs[gi]  = s01[gi] + s23[gi];
    }
    // block reduce -> full row sum rs (single barrier; every thread sums sred
    // itself in the SAME linear order -> bitwise-identical to the t0 path)
    __shared__ float sred[8];
    float tsum = (gs[0] + gs[1]) + (gs[2] + gs[3]);
    #pragma unroll
    for (int off = 16; off > 0; off >>= 1) tsum += __shfl_xor_sync(0xffffffffu, tsum, off);
    if ((t & 31) == 0) sred[t >> 5] = tsum;
    __syncthreads();
    float rsf = 0.f;
    #pragma unroll
    for (int ww = 0; ww < 8; ++ww) rsf += sred[ww];
    const float rsm = rsf - EXP10S;

    const int gcols[4] = {2 * t, 2 * t + 1, 512 + 2 * t, 513 + 2 * t};
    float acc = 0.f;
    #pragma unroll
    for (int gi = 0; gi < 4; ++gi) {
        const float* eg = &e[4 * gi];
        const float base = rsm - gs[gi];
        if (gcols[gi] != gr) {
            float pr = (base + s01[gi]) * (base + s23[gi]);
            pr *= (base + (eg[0] + eg[2]));
            pr *= (base + (eg[0] + eg[3]));
            pr *= (base + (eg[1] + eg[2]));
            pr *= (base + (eg[1] + eg[3]));
            acc += __logf(pr);
        } else {
            const float b2 = base + eg[kk];
            float pr = 1.f;
            #pragma unroll
            for (int m = 0; m < 4; ++m)
                if (m != kk) pr *= (b2 + eg[m]);
            acc += __logf(pr);
        }
    }

    #pragma unroll
    for (int off = 16; off > 0; off >>= 1) acc += __shfl_down_sync(0xffffffffu, acc, off);
    __shared__ float wa[8];
    if ((t & 31) == 0) wa[t >> 5] = acc;
    __syncthreads();
    if (t == 0) {
        float a = 0.f;
        #pragma unroll
        for (int ww = 0; ww < 8; ++ww) a += wa[ww];
        g_rowL[r] = a;
    }
}

// ---------------- kernel 3: parallel deterministic combine -----------------
__global__ void k_finalize(float* __restrict__ out) {
    const int t = threadIdx.x;
    const float4* p = reinterpret_cast<const float4*>(g_rowL);

    float4 v0 = p[t], v1 = p[t + 256], v2 = p[t + 512], v3 = p[t + 768];
    double a = (double)((v0.x + v0.y) + (v0.z + v0.w))
             + (double)((v1.x + v1.y) + (v1.z + v1.w))
             + (double)((v2.x + v2.y) + (v2.z + v2.w))
             + (double)((v3.x + v3.y) + (v3.z + v3.w));

    #pragma unroll
    for (int off = 16; off > 0; off >>= 1) a += __shfl_down_sync(0xffffffffu, a, off);
    __shared__ double sa[8];
    if ((t & 31) == 0) sa[t >> 5] = a;
    __syncthreads();

    if (t < 32) {
        double s = (t < 8) ? sa[t] : 0.0;
        #pragma unroll
        for (int off = 4; off > 0; off >>= 1) s += __shfl_down_sync(0xffffffffu, s, off);
        double pd = (double)g_Pdiag[t];
        #pragma unroll
        for (int off = 16; off > 0; off >>= 1) pd += __shfl_down_sync(0xffffffffu, pd, off);
        if (t == 0) out[0] = (float)(s * (2.0 / 4094.0) - pd);
    }
}

// ---------------- launch ---------------------------------------------------
extern "C" void kernel_launch(void* const* d_in, const int* in_sizes, int n_in,
                              void* d_out, int out_size) {
    const float* feats = (const float*)d_in[0];
    float* out = (float*)d_out;

    cudaFuncSetAttribute(k_gemm_exp, cudaFuncAttributeMaxDynamicSharedMemorySize, SMEM2);

    k_gemm_exp<<<528, 256, SMEM2>>>(feats);
    k_loss<<<NSEG, 256>>>();
    k_finalize<<<1, 256>>>(out);
}